// round 4
// baseline (speedup 1.0000x reference)
#include <cuda_runtime.h>
#include <math.h>

#define SS 512
#define BB 64
#define II 1024
#define HH 1024
#define G4 4096   // 4*H

// Scratch: xW for all timesteps (fp32), and ping-pong cell state.
__device__ float g_xw[(size_t)SS * BB * G4];   // 512 MB
__device__ float g_c[2][BB * HH];

__device__ __forceinline__ float sigf(float x) {
    return 1.0f / (1.0f + __expf(-x));
}

// ---------------------------------------------------------------------------
// Kernel A: g_xw[m, g] = sum_i X[m, i] * W[g, i] + bias[g]
//   Tile: BM=64, BN=64, BK=32, 256 threads, 4x4 per thread. (unchanged)
// ---------------------------------------------------------------------------
__global__ __launch_bounds__(256) void gemm_xw(const float* __restrict__ X,
                                               const float* __restrict__ W,
                                               const float* __restrict__ bias) {
    __shared__ __align__(16) float As[32][68];
    __shared__ __align__(16) float Bs[32][68];

    const int m0 = blockIdx.y * 64;
    const int n0 = blockIdx.x * 64;
    const int tid = threadIdx.x;
    const int tx = tid & 15;
    const int ty = tid >> 4;
    const int r  = tid >> 3;
    const int kv = (tid & 7) << 2;

    float acc[4][4] = {};

    for (int k0 = 0; k0 < II; k0 += 32) {
        float4 a0 = *(const float4*)(X + (size_t)(m0 + r)      * II + k0 + kv);
        float4 a1 = *(const float4*)(X + (size_t)(m0 + r + 32) * II + k0 + kv);
        float4 b0 = *(const float4*)(W + (size_t)(n0 + r)      * II + k0 + kv);
        float4 b1 = *(const float4*)(W + (size_t)(n0 + r + 32) * II + k0 + kv);

        As[kv+0][r] = a0.x; As[kv+1][r] = a0.y; As[kv+2][r] = a0.z; As[kv+3][r] = a0.w;
        As[kv+0][r+32] = a1.x; As[kv+1][r+32] = a1.y; As[kv+2][r+32] = a1.z; As[kv+3][r+32] = a1.w;
        Bs[kv+0][r] = b0.x; Bs[kv+1][r] = b0.y; Bs[kv+2][r] = b0.z; Bs[kv+3][r] = b0.w;
        Bs[kv+0][r+32] = b1.x; Bs[kv+1][r+32] = b1.y; Bs[kv+2][r+32] = b1.z; Bs[kv+3][r+32] = b1.w;
        __syncthreads();

        #pragma unroll
        for (int k = 0; k < 32; k++) {
            float4 av = *(const float4*)&As[k][ty << 2];
            float4 bv = *(const float4*)&Bs[k][tx << 2];
            float am[4] = {av.x, av.y, av.z, av.w};
            float bn[4] = {bv.x, bv.y, bv.z, bv.w};
            #pragma unroll
            for (int i = 0; i < 4; i++)
                #pragma unroll
                for (int j = 0; j < 4; j++)
                    acc[i][j] += am[i] * bn[j];
        }
        __syncthreads();
    }

    const int nn = n0 + (tx << 2);
    float4 bsv = *(const float4*)(bias + nn);
    float bb4[4] = {bsv.x, bsv.y, bsv.z, bsv.w};
    #pragma unroll
    for (int i = 0; i < 4; i++) {
        const int m = m0 + (ty << 2) + i;
        float4 ov;
        ov.x = acc[i][0] + bb4[0];
        ov.y = acc[i][1] + bb4[1];
        ov.z = acc[i][2] + bb4[2];
        ov.w = acc[i][3] + bb4[3];
        *(float4*)(g_xw + (size_t)m * G4 + nn) = ov;
    }
}

// ---------------------------------------------------------------------------
// Kernel B (v2): one LSTM step, fused GEMM + gates.
//   Tile 32 batch x 64 gate-cols, 256 threads (8 warps), thread tile 2x4.
//   Register-prefetch double buffering of the global->smem loads so L2
//   latency is hidden behind the 32-k FFMA stage.
// ---------------------------------------------------------------------------
__global__ __launch_bounds__(256) void lstm_step(const float* __restrict__ hprev,
                                                 const float* __restrict__ U,
                                                 int t, int par,
                                                 float* __restrict__ hout) {
    __shared__ __align__(16) float Hs[32][36];   // [k][m]
    __shared__ __align__(16) float Us[32][68];   // [k][c]
    __shared__ __align__(16) float gbuf[32][68];

    const int nb = blockIdx.x;            // 0..63
    const int m0 = blockIdx.y << 5;       // 0 or 32
    const int tid = threadIdx.x;          // 256
    const int tx = tid & 15;              // 0..15 -> c group (4 cols)
    const int ty = tid >> 4;              // 0..15 -> m pair (2 rows)

    // Loader indices
    const int hr = tid >> 3;              // 0..31 (batch row)
    const int hk = (tid & 7) << 2;        // 0..28 (k within stage)
    const int uc = tid >> 2;              // 0..63 (gate col)
    const int uk = (tid & 3) << 2;        // 0,4,8,12
    const int uG = ((uc >> 4) << 10) + (nb << 4) + (uc & 15);

    const float* hP = hprev + (size_t)(m0 + hr) * HH + hk;
    const float* uP = U + (size_t)uG * HH + uk;

    // Prefetch stage 0
    float4 ha = *(const float4*)(hP);
    float4 u0 = *(const float4*)(uP);
    float4 u1 = *(const float4*)(uP + 16);

    float acc[2][4] = {};

    for (int k0 = 0; k0 < HH; k0 += 32) {
        // Commit prefetched stage to smem
        Hs[hk+0][hr] = ha.x; Hs[hk+1][hr] = ha.y;
        Hs[hk+2][hr] = ha.z; Hs[hk+3][hr] = ha.w;
        Us[uk+0][uc]  = u0.x; Us[uk+1][uc]  = u0.y;
        Us[uk+2][uc]  = u0.z; Us[uk+3][uc]  = u0.w;
        Us[uk+16][uc] = u1.x; Us[uk+17][uc] = u1.y;
        Us[uk+18][uc] = u1.z; Us[uk+19][uc] = u1.w;
        __syncthreads();

        // Issue next-stage global loads (latency hidden behind compute)
        if (k0 + 32 < HH) {
            ha = *(const float4*)(hP + k0 + 32);
            u0 = *(const float4*)(uP + k0 + 32);
            u1 = *(const float4*)(uP + k0 + 48);
        }

        #pragma unroll
        for (int k = 0; k < 32; k++) {
            const float2 av = *(const float2*)&Hs[k][ty << 1];
            const float4 bv = *(const float4*)&Us[k][tx << 2];
            acc[0][0] += av.x * bv.x; acc[0][1] += av.x * bv.y;
            acc[0][2] += av.x * bv.z; acc[0][3] += av.x * bv.w;
            acc[1][0] += av.y * bv.x; acc[1][1] += av.y * bv.y;
            acc[1][2] += av.y * bv.z; acc[1][3] += av.y * bv.w;
        }
        __syncthreads();
    }

    // Add xW contribution, stage gates in smem.
    const int Gbase = ((tx >> 2) << 10) + (nb << 4) + ((tx & 3) << 2);
    #pragma unroll
    for (int i = 0; i < 2; i++) {
        const int m = (ty << 1) + i;
        const float4 xw = *(const float4*)(g_xw +
            ((size_t)t * BB + m0 + m) * G4 + Gbase);
        float4 gv;
        gv.x = acc[i][0] + xw.x;
        gv.y = acc[i][1] + xw.y;
        gv.z = acc[i][2] + xw.z;
        gv.w = acc[i][3] + xw.w;
        *(float4*)&gbuf[m][tx << 2] = gv;
    }
    __syncthreads();

    // Fused elementwise: 32 rows x 16 j = 512 items / 256 threads = 2 each.
    const float* cprev = g_c[par];
    float* cout = g_c[par ^ 1];
    #pragma unroll
    for (int q = 0; q < 2; q++) {
        const int p = tid + (q << 8);     // 0..511
        const int bm = p >> 4;            // 0..31
        const int jj = p & 15;
        const float iv = sigf(gbuf[bm][jj]);
        const float fv = sigf(gbuf[bm][16 + jj]);
        const float gv = tanhf(gbuf[bm][32 + jj]);
        const float ov = sigf(gbuf[bm][48 + jj]);
        const int idx = (m0 + bm) * HH + (nb << 4) + jj;
        const float cn = fv * cprev[idx] + iv * gv;
        cout[idx] = cn;
        hout[idx] = ov * tanhf(cn);
    }
}

// ---------------------------------------------------------------------------
// Small helpers: seed c buffer, emit h_t / c_t tails.
// ---------------------------------------------------------------------------
__global__ void copy_c0(const float* __restrict__ c0) {
    const int i = blockIdx.x * 256 + threadIdx.x;
    g_c[0][i] = c0[i];
}

__global__ void finalize(float* __restrict__ out) {
    const int i = blockIdx.x * 256 + threadIdx.x;
    const size_t base = (size_t)SS * BB * HH;
    out[base + i] = out[(size_t)(SS - 1) * BB * HH + i];   // h_t
    out[base + BB * HH + i] = g_c[0][i];                   // c_t (S even -> final in g_c[0])
}

// ---------------------------------------------------------------------------
extern "C" void kernel_launch(void* const* d_in, const int* in_sizes, int n_in,
                              void* d_out, int out_size) {
    (void)in_sizes; (void)n_in; (void)out_size;
    const float* x  = (const float*)d_in[0];
    const float* h0 = (const float*)d_in[1];
    const float* c0 = (const float*)d_in[2];
    const float* Ww = (const float*)d_in[3];
    const float* Wb = (const float*)d_in[4];
    const float* Uw = (const float*)d_in[5];
    float* out = (float*)d_out;

    copy_c0<<<(BB * HH) / 256, 256>>>(c0);

    gemm_xw<<<dim3(G4 / 64, (SS * BB) / 64), 256>>>(x, Ww, Wb);

    for (int t = 0; t < SS; t++) {
        const float* hp = (t == 0) ? h0 : (out + (size_t)(t - 1) * BB * HH);
        lstm_step<<<dim3(HH / 16, BB / 32), 256>>>(hp, Uw, t, t & 1,
                                                   out + (size_t)t * BB * HH);
    }

    finalize<<<(BB * HH) / 256, 256>>>(out);
}

// round 5
// speedup vs baseline: 1.0487x; 1.0487x over previous
#include <cuda_runtime.h>
#include <math.h>

#define SS 512
#define BB 64
#define II 1024
#define HH 1024
#define G4 4096   // 4*H

// Scratch: xW for all timesteps (fp32), and ping-pong cell state.
__device__ float g_xw[(size_t)SS * BB * G4];   // 512 MB
__device__ float g_c[2][BB * HH];

__device__ __forceinline__ float sigf(float x) {
    return 1.0f / (1.0f + __expf(-x));
}

// ---------------------------------------------------------------------------
// Kernel A: g_xw[m, g] = sum_i X[m, i] * W[g, i] + bias[g]
//   Tile: BM=64, BN=64, BK=32, 256 threads, 4x4 per thread. (unchanged)
// ---------------------------------------------------------------------------
__global__ __launch_bounds__(256) void gemm_xw(const float* __restrict__ X,
                                               const float* __restrict__ W,
                                               const float* __restrict__ bias) {
    __shared__ __align__(16) float As[32][68];
    __shared__ __align__(16) float Bs[32][68];

    const int m0 = blockIdx.y * 64;
    const int n0 = blockIdx.x * 64;
    const int tid = threadIdx.x;
    const int tx = tid & 15;
    const int ty = tid >> 4;
    const int r  = tid >> 3;
    const int kv = (tid & 7) << 2;

    float acc[4][4] = {};

    for (int k0 = 0; k0 < II; k0 += 32) {
        float4 a0 = *(const float4*)(X + (size_t)(m0 + r)      * II + k0 + kv);
        float4 a1 = *(const float4*)(X + (size_t)(m0 + r + 32) * II + k0 + kv);
        float4 b0 = *(const float4*)(W + (size_t)(n0 + r)      * II + k0 + kv);
        float4 b1 = *(const float4*)(W + (size_t)(n0 + r + 32) * II + k0 + kv);

        As[kv+0][r] = a0.x; As[kv+1][r] = a0.y; As[kv+2][r] = a0.z; As[kv+3][r] = a0.w;
        As[kv+0][r+32] = a1.x; As[kv+1][r+32] = a1.y; As[kv+2][r+32] = a1.z; As[kv+3][r+32] = a1.w;
        Bs[kv+0][r] = b0.x; Bs[kv+1][r] = b0.y; Bs[kv+2][r] = b0.z; Bs[kv+3][r] = b0.w;
        Bs[kv+0][r+32] = b1.x; Bs[kv+1][r+32] = b1.y; Bs[kv+2][r+32] = b1.z; Bs[kv+3][r+32] = b1.w;
        __syncthreads();

        #pragma unroll
        for (int k = 0; k < 32; k++) {
            float4 av = *(const float4*)&As[k][ty << 2];
            float4 bv = *(const float4*)&Bs[k][tx << 2];
            float am[4] = {av.x, av.y, av.z, av.w};
            float bn[4] = {bv.x, bv.y, bv.z, bv.w};
            #pragma unroll
            for (int i = 0; i < 4; i++)
                #pragma unroll
                for (int j = 0; j < 4; j++)
                    acc[i][j] += am[i] * bn[j];
        }
        __syncthreads();
    }

    const int nn = n0 + (tx << 2);
    float4 bsv = *(const float4*)(bias + nn);
    float bb4[4] = {bsv.x, bsv.y, bsv.z, bsv.w};
    #pragma unroll
    for (int i = 0; i < 4; i++) {
        const int m = m0 + (ty << 2) + i;
        float4 ov;
        ov.x = acc[i][0] + bb4[0];
        ov.y = acc[i][1] + bb4[1];
        ov.z = acc[i][2] + bb4[2];
        ov.w = acc[i][3] + bb4[3];
        *(float4*)(g_xw + (size_t)m * G4 + nn) = ov;
    }
}

// ---------------------------------------------------------------------------
// Kernel B (v2): one LSTM step, fused GEMM + gates.
//   Tile 32 batch x 64 gate-cols, 256 threads (8 warps), thread tile 2x4.
//   Register-prefetch double buffering of the global->smem loads so L2
//   latency is hidden behind the 32-k FFMA stage.
// ---------------------------------------------------------------------------
__global__ __launch_bounds__(256) void lstm_step(const float* __restrict__ hprev,
                                                 const float* __restrict__ U,
                                                 int t, int par,
                                                 float* __restrict__ hout) {
    __shared__ __align__(16) float Hs[32][36];   // [k][m]
    __shared__ __align__(16) float Us[32][68];   // [k][c]
    __shared__ __align__(16) float gbuf[32][68];

    const int nb = blockIdx.x;            // 0..63
    const int m0 = blockIdx.y << 5;       // 0 or 32
    const int tid = threadIdx.x;          // 256
    const int tx = tid & 15;              // 0..15 -> c group (4 cols)
    const int ty = tid >> 4;              // 0..15 -> m pair (2 rows)

    // Loader indices
    const int hr = tid >> 3;              // 0..31 (batch row)
    const int hk = (tid & 7) << 2;        // 0..28 (k within stage)
    const int uc = tid >> 2;              // 0..63 (gate col)
    const int uk = (tid & 3) << 2;        // 0,4,8,12
    const int uG = ((uc >> 4) << 10) + (nb << 4) + (uc & 15);

    const float* hP = hprev + (size_t)(m0 + hr) * HH + hk;
    const float* uP = U + (size_t)uG * HH + uk;

    // Prefetch stage 0
    float4 ha = *(const float4*)(hP);
    float4 u0 = *(const float4*)(uP);
    float4 u1 = *(const float4*)(uP + 16);

    float acc[2][4] = {};

    for (int k0 = 0; k0 < HH; k0 += 32) {
        // Commit prefetched stage to smem
        Hs[hk+0][hr] = ha.x; Hs[hk+1][hr] = ha.y;
        Hs[hk+2][hr] = ha.z; Hs[hk+3][hr] = ha.w;
        Us[uk+0][uc]  = u0.x; Us[uk+1][uc]  = u0.y;
        Us[uk+2][uc]  = u0.z; Us[uk+3][uc]  = u0.w;
        Us[uk+16][uc] = u1.x; Us[uk+17][uc] = u1.y;
        Us[uk+18][uc] = u1.z; Us[uk+19][uc] = u1.w;
        __syncthreads();

        // Issue next-stage global loads (latency hidden behind compute)
        if (k0 + 32 < HH) {
            ha = *(const float4*)(hP + k0 + 32);
            u0 = *(const float4*)(uP + k0 + 32);
            u1 = *(const float4*)(uP + k0 + 48);
        }

        #pragma unroll
        for (int k = 0; k < 32; k++) {
            const float2 av = *(const float2*)&Hs[k][ty << 1];
            const float4 bv = *(const float4*)&Us[k][tx << 2];
            acc[0][0] += av.x * bv.x; acc[0][1] += av.x * bv.y;
            acc[0][2] += av.x * bv.z; acc[0][3] += av.x * bv.w;
            acc[1][0] += av.y * bv.x; acc[1][1] += av.y * bv.y;
            acc[1][2] += av.y * bv.z; acc[1][3] += av.y * bv.w;
        }
        __syncthreads();
    }

    // Add xW contribution, stage gates in smem.
    const int Gbase = ((tx >> 2) << 10) + (nb << 4) + ((tx & 3) << 2);
    #pragma unroll
    for (int i = 0; i < 2; i++) {
        const int m = (ty << 1) + i;
        const float4 xw = *(const float4*)(g_xw +
            ((size_t)t * BB + m0 + m) * G4 + Gbase);
        float4 gv;
        gv.x = acc[i][0] + xw.x;
        gv.y = acc[i][1] + xw.y;
        gv.z = acc[i][2] + xw.z;
        gv.w = acc[i][3] + xw.w;
        *(float4*)&gbuf[m][tx << 2] = gv;
    }
    __syncthreads();

    // Fused elementwise: 32 rows x 16 j = 512 items / 256 threads = 2 each.
    const float* cprev = g_c[par];
    float* cout = g_c[par ^ 1];
    #pragma unroll
    for (int q = 0; q < 2; q++) {
        const int p = tid + (q << 8);     // 0..511
        const int bm = p >> 4;            // 0..31
        const int jj = p & 15;
        const float iv = sigf(gbuf[bm][jj]);
        const float fv = sigf(gbuf[bm][16 + jj]);
        const float gv = tanhf(gbuf[bm][32 + jj]);
        const float ov = sigf(gbuf[bm][48 + jj]);
        const int idx = (m0 + bm) * HH + (nb << 4) + jj;
        const float cn = fv * cprev[idx] + iv * gv;
        cout[idx] = cn;
        hout[idx] = ov * tanhf(cn);
    }
}

// ---------------------------------------------------------------------------
// Small helpers: seed c buffer, emit h_t / c_t tails.
// ---------------------------------------------------------------------------
__global__ void copy_c0(const float* __restrict__ c0) {
    const int i = blockIdx.x * 256 + threadIdx.x;
    g_c[0][i] = c0[i];
}

__global__ void finalize(float* __restrict__ out) {
    const int i = blockIdx.x * 256 + threadIdx.x;
    const size_t base = (size_t)SS * BB * HH;
    out[base + i] = out[(size_t)(SS - 1) * BB * HH + i];   // h_t
    out[base + BB * HH + i] = g_c[0][i];                   // c_t (S even -> final in g_c[0])
}

// ---------------------------------------------------------------------------
extern "C" void kernel_launch(void* const* d_in, const int* in_sizes, int n_in,
                              void* d_out, int out_size) {
    (void)in_sizes; (void)n_in; (void)out_size;
    const float* x  = (const float*)d_in[0];
    const float* h0 = (const float*)d_in[1];
    const float* c0 = (const float*)d_in[2];
    const float* Ww = (const float*)d_in[3];
    const float* Wb = (const float*)d_in[4];
    const float* Uw = (const float*)d_in[5];
    float* out = (float*)d_out;

    copy_c0<<<(BB * HH) / 256, 256>>>(c0);

    gemm_xw<<<dim3(G4 / 64, (SS * BB) / 64), 256>>>(x, Ww, Wb);

    for (int t = 0; t < SS; t++) {
        const float* hp = (t == 0) ? h0 : (out + (size_t)(t - 1) * BB * HH);
        lstm_step<<<dim3(HH / 16, BB / 32), 256>>>(hp, Uw, t, t & 1,
                                                   out + (size_t)t * BB * HH);
    }

    finalize<<<(BB * HH) / 256, 256>>>(out);
}

// round 7
// speedup vs baseline: 1.1696x; 1.1152x over previous
#include <cuda_runtime.h>
#include <math.h>

#define SS 512
#define BB 64
#define II 1024
#define HH 1024
#define G4 4096   // 4*H

#define NKB 8          // K-split factor for the step GEMM
#define NNB 16         // n-blocks (gate-coherent, 64 h-cols each)
#define BKC 128        // k-span per step-GEMM block (1024/8)
#define BKS 16         // k per smem stage

// Scratch: xW for all timesteps, k-split partials, ping-pong cell state.
__device__ float g_xw[(size_t)SS * BB * G4];       // 512 MB
__device__ float g_part[NKB][BB * G4];             // 8 MB
__device__ float g_c[2][BB * HH];
__device__ int   g_done[NNB];

__device__ __forceinline__ float sigf(float x) {
    return 1.0f / (1.0f + __expf(-x));
}
// tanh(x) = 2*sigmoid(2x) - 1  (fast __expf path, ~1e-6 abs err)
__device__ __forceinline__ float tanhfast(float x) {
    return fmaf(2.0f, sigf(2.0f * x), -1.0f);
}

typedef unsigned long long ull;

__device__ __forceinline__ void fma2(ull& d, ull a, ull b) {
    asm("fma.rn.f32x2 %0, %1, %2, %0;" : "+l"(d) : "l"(a), "l"(b));
}
__device__ __forceinline__ float2 u2f(ull v) {
    float2 r;
    asm("mov.b64 {%0, %1}, %2;" : "=f"(r.x), "=f"(r.y) : "l"(v));
    return r;
}

// ---------------------------------------------------------------------------
// Kernel A: g_xw[m, g] = sum_i X[m, i] * W[g, i] + bias[g]   (unchanged)
// ---------------------------------------------------------------------------
__global__ __launch_bounds__(256) void gemm_xw(const float* __restrict__ X,
                                               const float* __restrict__ W,
                                               const float* __restrict__ bias) {
    __shared__ __align__(16) float As[32][68];
    __shared__ __align__(16) float Bs[32][68];

    const int m0 = blockIdx.y * 64;
    const int n0 = blockIdx.x * 64;
    const int tid = threadIdx.x;
    const int tx = tid & 15;
    const int ty = tid >> 4;
    const int r  = tid >> 3;
    const int kv = (tid & 7) << 2;

    float acc[4][4] = {};

    for (int k0 = 0; k0 < II; k0 += 32) {
        float4 a0 = *(const float4*)(X + (size_t)(m0 + r)      * II + k0 + kv);
        float4 a1 = *(const float4*)(X + (size_t)(m0 + r + 32) * II + k0 + kv);
        float4 b0 = *(const float4*)(W + (size_t)(n0 + r)      * II + k0 + kv);
        float4 b1 = *(const float4*)(W + (size_t)(n0 + r + 32) * II + k0 + kv);

        As[kv+0][r] = a0.x; As[kv+1][r] = a0.y; As[kv+2][r] = a0.z; As[kv+3][r] = a0.w;
        As[kv+0][r+32] = a1.x; As[kv+1][r+32] = a1.y; As[kv+2][r+32] = a1.z; As[kv+3][r+32] = a1.w;
        Bs[kv+0][r] = b0.x; Bs[kv+1][r] = b0.y; Bs[kv+2][r] = b0.z; Bs[kv+3][r] = b0.w;
        Bs[kv+0][r+32] = b1.x; Bs[kv+1][r+32] = b1.y; Bs[kv+2][r+32] = b1.z; Bs[kv+3][r+32] = b1.w;
        __syncthreads();

        #pragma unroll
        for (int k = 0; k < 32; k++) {
            float4 av = *(const float4*)&As[k][ty << 2];
            float4 bv = *(const float4*)&Bs[k][tx << 2];
            float am[4] = {av.x, av.y, av.z, av.w};
            float bn[4] = {bv.x, bv.y, bv.z, bv.w};
            #pragma unroll
            for (int i = 0; i < 4; i++)
                #pragma unroll
                for (int j = 0; j < 4; j++)
                    acc[i][j] += am[i] * bn[j];
        }
        __syncthreads();
    }

    const int nn = n0 + (tx << 2);
    float4 bsv = *(const float4*)(bias + nn);
    float bb4[4] = {bsv.x, bsv.y, bsv.z, bsv.w};
    #pragma unroll
    for (int i = 0; i < 4; i++) {
        const int m = m0 + (ty << 2) + i;
        float4 ov;
        ov.x = acc[i][0] + bb4[0];
        ov.y = acc[i][1] + bb4[1];
        ov.z = acc[i][2] + bb4[2];
        ov.w = acc[i][3] + bb4[3];
        *(float4*)(g_xw + (size_t)m * G4 + nn) = ov;
    }
}

// ---------------------------------------------------------------------------
// Kernel B: fused LSTM step. grid (NNB=16, NKB=8), 256 threads.
//   Phase 1 (all 128 blocks): K-split partial GEMM, 64m x 256n x 128k,
//     packed-fp32 FFMA2, 8x8 thread tiles, A duplicated in smem.
//     n-tile is GATE-COHERENT: block nb owns gate-local cols
//     [nb*64, nb*64+64) of each of the 4 gates.
//   Phase 2 (last kb-block per nb, via threadfence+atomic counter):
//     sum 8 partials + xW, gates, c update, h write for its 64 h-cols.
//   Deterministic: fixed kb summation order, independent of arrival order.
// ---------------------------------------------------------------------------
__global__ __launch_bounds__(256) void step_fused(const float* __restrict__ hprev,
                                                  const float* __restrict__ U,
                                                  int t, int par,
                                                  float* __restrict__ hout) {
    __shared__ __align__(16) float Ad[BKS][140];    // h duplicated: [k][2m(+pad)]
    __shared__ __align__(16) float Bs[BKS][264];    // U: [k][c(+pad)]
    __shared__ int s_last;

    const int nb = blockIdx.x;            // 0..15
    const int kb = blockIdx.y;            // 0..7
    const int kbase = kb * BKC;
    const int tid = threadIdx.x;
    const int tx = tid & 31;              // n-group
    const int ty = tid >> 5;              // m-group (8 rows)

    // A loader: 64 rows x 16 k = 1 float4/thread
    const int ar = tid >> 2;                  // 0..63
    const int ak = (tid & 3) << 2;            // 0,4,8,12
    const float* aP = hprev + (size_t)ar * HH + kbase + ak;

    // B loader: 4 gate groups of 64 rows x 16 k.
    //   smem col c = 64*q + (tid>>2); global U row = q*1024 + nb*64 + (tid>>2)
    const int ur = tid >> 2;                  // 0..63 local row
    const int uk = (tid & 3) << 2;
    const float* uP = U + (size_t)((nb << 6) + ur) * HH + kbase + uk;
    const size_t ugstr = (size_t)1024 * HH;   // next gate

    // Prefetch stage 0
    float4 ha  = *(const float4*)(aP);
    float4 ub0 = *(const float4*)(uP);
    float4 ub1 = *(const float4*)(uP + ugstr);
    float4 ub2 = *(const float4*)(uP + 2 * ugstr);
    float4 ub3 = *(const float4*)(uP + 3 * ugstr);

    ull acc[8][4];
    #pragma unroll
    for (int i = 0; i < 8; i++)
        #pragma unroll
        for (int j = 0; j < 4; j++) acc[i][j] = 0ull;

    for (int s = 0; s < BKC; s += BKS) {
        #pragma unroll
        for (int i = 0; i < 4; i++) {
            const float av = (&ha.x)[i];
            Ad[ak + i][2 * ar]     = av;
            Ad[ak + i][2 * ar + 1] = av;
            Bs[uk + i][ur]       = (&ub0.x)[i];
            Bs[uk + i][ur + 64]  = (&ub1.x)[i];
            Bs[uk + i][ur + 128] = (&ub2.x)[i];
            Bs[uk + i][ur + 192] = (&ub3.x)[i];
        }
        __syncthreads();

        if (s + BKS < BKC) {
            ha  = *(const float4*)(aP + s + BKS);
            ub0 = *(const float4*)(uP + s + BKS);
            ub1 = *(const float4*)(uP + ugstr + s + BKS);
            ub2 = *(const float4*)(uP + 2 * ugstr + s + BKS);
            ub3 = *(const float4*)(uP + 3 * ugstr + s + BKS);
        }

        #pragma unroll
        for (int k = 0; k < BKS; k++) {
            ull a2[8];
            #pragma unroll
            for (int i2 = 0; i2 < 4; i2++) {
                const ulonglong2 aa =
                    *(const ulonglong2*)&Ad[k][(ty << 4) + (i2 << 2)];
                a2[2 * i2]     = aa.x;
                a2[2 * i2 + 1] = aa.y;
            }
            const ulonglong2 bb0 = *(const ulonglong2*)&Bs[k][tx << 2];
            const ulonglong2 bb1 = *(const ulonglong2*)&Bs[k][128 + (tx << 2)];
            ull b2[4] = {bb0.x, bb0.y, bb1.x, bb1.y};

            #pragma unroll
            for (int i = 0; i < 8; i++) {
                fma2(acc[i][0], a2[i], b2[0]);
                fma2(acc[i][1], a2[i], b2[1]);
                fma2(acc[i][2], a2[i], b2[2]);
                fma2(acc[i][3], a2[i], b2[3]);
            }
        }
        __syncthreads();
    }

    // Store partials at GLOBAL gate indices.
    //   smem col cA = tx*4 (gates 0/1), cB = 128 + tx*4 (gates 2/3)
    //   gidxA = (tx>>4)*1024 + nb*64 + (tx&15)*4 ; gidxB = gidxA + 2048
    {
        float* pout = g_part[kb];
        const int gidxA = ((tx >> 4) << 10) + (nb << 6) + ((tx & 15) << 2);
        #pragma unroll
        for (int i = 0; i < 8; i++) {
            const int m = (ty << 3) + i;
            const float2 p0 = u2f(acc[i][0]);
            const float2 p1 = u2f(acc[i][1]);
            const float2 p2 = u2f(acc[i][2]);
            const float2 p3 = u2f(acc[i][3]);
            float4 oA = {p0.x, p0.y, p1.x, p1.y};
            float4 oB = {p2.x, p2.y, p3.x, p3.y};
            *(float4*)(pout + (size_t)m * G4 + gidxA)        = oA;
            *(float4*)(pout + (size_t)m * G4 + gidxA + 2048) = oB;
        }
    }

    // Make partials visible, then elect the last kb-block of this nb group.
    __threadfence();
    __syncthreads();
    if (tid == 0) {
        const int old = atomicAdd(&g_done[nb], 1);
        s_last = (old == NKB - 1);
    }
    __syncthreads();
    if (!s_last) return;

    // Phase 2: combine + elementwise for h-cols [nb*64, nb*64+64), all 64 b.
    //   Thread: 4 batch rows x 4 consecutive cols (float4).
    const int c4 = (tid & 15) << 2;          // 0..60
    const int b0 = (tid >> 4) << 2;          // 0..60
    const float* cprev = g_c[par];
    float* cout = g_c[par ^ 1];

    #pragma unroll
    for (int bi = 0; bi < 4; bi++) {
        const int b = b0 + bi;
        float4 gate[4];
        #pragma unroll
        for (int g = 0; g < 4; g++) {
            const size_t off = (size_t)b * G4 + (g << 10) + (nb << 6) + c4;
            float4 s = *(const float4*)(g_xw + (size_t)t * BB * G4 + off);
            #pragma unroll
            for (int p = 0; p < NKB; p++) {
                const float4 pv = *(const float4*)(g_part[p] + off);
                s.x += pv.x; s.y += pv.y; s.z += pv.z; s.w += pv.w;
            }
            gate[g] = s;
        }

        const int idx = b * HH + (nb << 6) + c4;
        const float4 cp = *(const float4*)(cprev + idx);
        float4 cn, hv;
        {
            const float iv = sigf(gate[0].x), fv = sigf(gate[1].x);
            const float gv = tanhfast(gate[2].x), ov = sigf(gate[3].x);
            cn.x = fv * cp.x + iv * gv;  hv.x = ov * tanhfast(cn.x);
        }
        {
            const float iv = sigf(gate[0].y), fv = sigf(gate[1].y);
            const float gv = tanhfast(gate[2].y), ov = sigf(gate[3].y);
            cn.y = fv * cp.y + iv * gv;  hv.y = ov * tanhfast(cn.y);
        }
        {
            const float iv = sigf(gate[0].z), fv = sigf(gate[1].z);
            const float gv = tanhfast(gate[2].z), ov = sigf(gate[3].z);
            cn.z = fv * cp.z + iv * gv;  hv.z = ov * tanhfast(cn.z);
        }
        {
            const float iv = sigf(gate[0].w), fv = sigf(gate[1].w);
            const float gv = tanhfast(gate[2].w), ov = sigf(gate[3].w);
            cn.w = fv * cp.w + iv * gv;  hv.w = ov * tanhfast(cn.w);
        }
        *(float4*)(cout + idx) = cn;
        *(float4*)(hout + idx) = hv;
    }

    if (tid == 0) g_done[nb] = 0;   // reset for next step (launches serialize)
}

// ---------------------------------------------------------------------------
// Small helpers: seed c buffer + counters, emit h_t / c_t tails.
// ---------------------------------------------------------------------------
__global__ void copy_c0(const float* __restrict__ c0) {
    const int i = blockIdx.x * 256 + threadIdx.x;
    g_c[0][i] = c0[i];
    if (blockIdx.x == 0 && threadIdx.x < NNB) g_done[threadIdx.x] = 0;
}

__global__ void finalize(float* __restrict__ out) {
    const int i = blockIdx.x * 256 + threadIdx.x;
    const size_t base = (size_t)SS * BB * HH;
    out[base + i] = out[(size_t)(SS - 1) * BB * HH + i];   // h_t
    out[base + BB * HH + i] = g_c[0][i];                   // c_t (S even)
}

// ---------------------------------------------------------------------------
extern "C" void kernel_launch(void* const* d_in, const int* in_sizes, int n_in,
                              void* d_out, int out_size) {
    (void)in_sizes; (void)n_in; (void)out_size;
    const float* x  = (const float*)d_in[0];
    const float* h0 = (const float*)d_in[1];
    const float* c0 = (const float*)d_in[2];
    const float* Ww = (const float*)d_in[3];
    const float* Wb = (const float*)d_in[4];
    const float* Uw = (const float*)d_in[5];
    float* out = (float*)d_out;

    copy_c0<<<(BB * HH) / 256, 256>>>(c0);

    gemm_xw<<<dim3(G4 / 64, (SS * BB) / 64), 256>>>(x, Ww, Wb);

    for (int t = 0; t < SS; t++) {
        const float* hp = (t == 0) ? h0 : (out + (size_t)(t - 1) * BB * HH);
        step_fused<<<dim3(NNB, NKB), 256>>>(hp, Uw, t, t & 1,
                                            out + (size_t)t * BB * HH);
    }

    finalize<<<(BB * HH) / 256, 256>>>(out);
}

// round 8
// speedup vs baseline: 1.4470x; 1.2372x over previous
#include <cuda_runtime.h>
#include <math.h>

#define SS 512
#define BB 64
#define II 1024
#define HH 1024
#define G4 4096   // 4*H
#define BHH (BB * HH)

#define NKB 8          // K-split factor for the step GEMM
#define NNB 16         // n-blocks (gate-coherent, 64 h-cols each)
#define BKC 128        // k-span per step-GEMM block (1024/8)
#define BKS 16         // k per smem stage

// Scratch: xW for all timesteps, k-split partials, ping-pong cell state.
__device__ float g_xw[(size_t)SS * BB * G4];       // 512 MB
__device__ float g_part[NKB][BB * G4];             // 8 MB
__device__ float g_c[2][BHH];
__device__ unsigned g_nbcnt[NNB];                  // monotonic per-step-step
__device__ unsigned g_stepcnt;                     // monotonic

__device__ __forceinline__ float sigf(float x) {
    return 1.0f / (1.0f + __expf(-x));
}
__device__ __forceinline__ float tanhfast(float x) {
    return fmaf(2.0f, sigf(2.0f * x), -1.0f);
}

typedef unsigned long long ull;

__device__ __forceinline__ void fma2(ull& d, ull a, ull b) {
    asm("fma.rn.f32x2 %0, %1, %2, %0;" : "+l"(d) : "l"(a), "l"(b));
}
__device__ __forceinline__ float2 u2f(ull v) {
    float2 r;
    asm("mov.b64 {%0, %1}, %2;" : "=f"(r.x), "=f"(r.y) : "l"(v));
    return r;
}

// ---------------------------------------------------------------------------
// Kernel A: g_xw[m, g] = sum_i X[m, i] * W[g, i] + bias[g]   (unchanged)
// ---------------------------------------------------------------------------
__global__ __launch_bounds__(256) void gemm_xw(const float* __restrict__ X,
                                               const float* __restrict__ W,
                                               const float* __restrict__ bias) {
    __shared__ __align__(16) float As[32][68];
    __shared__ __align__(16) float Bs[32][68];

    const int m0 = blockIdx.y * 64;
    const int n0 = blockIdx.x * 64;
    const int tid = threadIdx.x;
    const int tx = tid & 15;
    const int ty = tid >> 4;
    const int r  = tid >> 3;
    const int kv = (tid & 7) << 2;

    float acc[4][4] = {};

    for (int k0 = 0; k0 < II; k0 += 32) {
        float4 a0 = *(const float4*)(X + (size_t)(m0 + r)      * II + k0 + kv);
        float4 a1 = *(const float4*)(X + (size_t)(m0 + r + 32) * II + k0 + kv);
        float4 b0 = *(const float4*)(W + (size_t)(n0 + r)      * II + k0 + kv);
        float4 b1 = *(const float4*)(W + (size_t)(n0 + r + 32) * II + k0 + kv);

        As[kv+0][r] = a0.x; As[kv+1][r] = a0.y; As[kv+2][r] = a0.z; As[kv+3][r] = a0.w;
        As[kv+0][r+32] = a1.x; As[kv+1][r+32] = a1.y; As[kv+2][r+32] = a1.z; As[kv+3][r+32] = a1.w;
        Bs[kv+0][r] = b0.x; Bs[kv+1][r] = b0.y; Bs[kv+2][r] = b0.z; Bs[kv+3][r] = b0.w;
        Bs[kv+0][r+32] = b1.x; Bs[kv+1][r+32] = b1.y; Bs[kv+2][r+32] = b1.z; Bs[kv+3][r+32] = b1.w;
        __syncthreads();

        #pragma unroll
        for (int k = 0; k < 32; k++) {
            float4 av = *(const float4*)&As[k][ty << 2];
            float4 bv = *(const float4*)&Bs[k][tx << 2];
            float am[4] = {av.x, av.y, av.z, av.w};
            float bn[4] = {bv.x, bv.y, bv.z, bv.w};
            #pragma unroll
            for (int i = 0; i < 4; i++)
                #pragma unroll
                for (int j = 0; j < 4; j++)
                    acc[i][j] += am[i] * bn[j];
        }
        __syncthreads();
    }

    const int nn = n0 + (tx << 2);
    float4 bsv = *(const float4*)(bias + nn);
    float bb4[4] = {bsv.x, bsv.y, bsv.z, bsv.w};
    #pragma unroll
    for (int i = 0; i < 4; i++) {
        const int m = m0 + (ty << 2) + i;
        float4 ov;
        ov.x = acc[i][0] + bb4[0];
        ov.y = acc[i][1] + bb4[1];
        ov.z = acc[i][2] + bb4[2];
        ov.w = acc[i][3] + bb4[3];
        *(float4*)(g_xw + (size_t)m * G4 + nn) = ov;
    }
}

// ---------------------------------------------------------------------------
// Kernel B: PERSISTENT LSTM — one launch runs all 512 steps.
//   128 blocks (single wave, guaranteed co-resident), 256 threads.
//   Block bid: nb = bid>>3 (gate-coherent 64 h-cols), kb = bid&7 (k-split).
//   Per step:
//     Phase 1: partial GEMM 64m x 256n x 128k, FFMA2, 8x8 thread tiles.
//              U is L1-resident after step 0 (L1 persists within launch).
//     nb-group sync via monotonic counter, then ALL 8 kb-blocks combine
//              (8 h-cols each): sum partials (__ldcg) + xW, gates, c, h.
//     Grid step barrier via monotonic counter before next step reads h.
// ---------------------------------------------------------------------------
__global__ __launch_bounds__(256) void lstm_persist(const float* __restrict__ h0,
                                                    const float* __restrict__ U,
                                                    float* __restrict__ out) {
    __shared__ __align__(16) float Ad[BKS][140];    // h duplicated: [k][2m(+pad)]
    __shared__ __align__(16) float Bs[BKS][264];    // U: [k][c(+pad)]

    const int bid = blockIdx.x;
    const int nb = bid >> 3;              // 0..15
    const int kb = bid & 7;               // 0..7
    const int kbase = kb * BKC;
    const int tid = threadIdx.x;
    const int tx = tid & 31;              // n-group
    const int ty = tid >> 5;              // m-group (8 rows)

    // A loader indices
    const int ar = tid >> 2;                  // 0..63
    const int ak = (tid & 3) << 2;            // 0,4,8,12

    // B loader: 4 gate groups of 64 rows x 16 k
    const int ur = tid >> 2;
    const int uk = (tid & 3) << 2;
    const float* uP = U + (size_t)((nb << 6) + ur) * HH + kbase + uk;
    const size_t ugstr = (size_t)1024 * HH;   // next gate

    // Partial store indices
    const int gidxA = ((tx >> 4) << 10) + (nb << 6) + ((tx & 15) << 2);

    // Combine indices: h-cols [nb*64 + kb*8, +8)
    const int cb  = tid >> 2;                 // batch 0..63
    const int hcol = (nb << 6) + (kb << 3) + ((tid & 3) << 1);

    for (int t = 0; t < SS; t++) {
        const float* hprev = t ? (out + (size_t)(t - 1) * BHH) : h0;
        const int par = t & 1;

        // ---------------- Phase 1: partial GEMM ----------------
        const float* aP = hprev + (size_t)ar * HH + kbase + ak;

        float4 ha  = *(const float4*)(aP);
        float4 ub0 = *(const float4*)(uP);
        float4 ub1 = *(const float4*)(uP + ugstr);
        float4 ub2 = *(const float4*)(uP + 2 * ugstr);
        float4 ub3 = *(const float4*)(uP + 3 * ugstr);

        ull acc[8][4];
        #pragma unroll
        for (int i = 0; i < 8; i++)
            #pragma unroll
            for (int j = 0; j < 4; j++) acc[i][j] = 0ull;

        for (int s = 0; s < BKC; s += BKS) {
            #pragma unroll
            for (int i = 0; i < 4; i++) {
                const float av = (&ha.x)[i];
                Ad[ak + i][2 * ar]     = av;
                Ad[ak + i][2 * ar + 1] = av;
                Bs[uk + i][ur]       = (&ub0.x)[i];
                Bs[uk + i][ur + 64]  = (&ub1.x)[i];
                Bs[uk + i][ur + 128] = (&ub2.x)[i];
                Bs[uk + i][ur + 192] = (&ub3.x)[i];
            }
            __syncthreads();

            if (s + BKS < BKC) {
                ha  = *(const float4*)(aP + s + BKS);
                ub0 = *(const float4*)(uP + s + BKS);
                ub1 = *(const float4*)(uP + ugstr + s + BKS);
                ub2 = *(const float4*)(uP + 2 * ugstr + s + BKS);
                ub3 = *(const float4*)(uP + 3 * ugstr + s + BKS);
            }

            #pragma unroll
            for (int k = 0; k < BKS; k++) {
                ull a2[8];
                #pragma unroll
                for (int i2 = 0; i2 < 4; i2++) {
                    const ulonglong2 aa =
                        *(const ulonglong2*)&Ad[k][(ty << 4) + (i2 << 2)];
                    a2[2 * i2]     = aa.x;
                    a2[2 * i2 + 1] = aa.y;
                }
                const ulonglong2 bb0 = *(const ulonglong2*)&Bs[k][tx << 2];
                const ulonglong2 bb1 = *(const ulonglong2*)&Bs[k][128 + (tx << 2)];
                ull b2[4] = {bb0.x, bb0.y, bb1.x, bb1.y};

                #pragma unroll
                for (int i = 0; i < 8; i++) {
                    fma2(acc[i][0], a2[i], b2[0]);
                    fma2(acc[i][1], a2[i], b2[1]);
                    fma2(acc[i][2], a2[i], b2[2]);
                    fma2(acc[i][3], a2[i], b2[3]);
                }
            }
            __syncthreads();
        }

        // Store partials at global gate indices.
        {
            float* pout = g_part[kb];
            #pragma unroll
            for (int i = 0; i < 8; i++) {
                const int m = (ty << 3) + i;
                const float2 p0 = u2f(acc[i][0]);
                const float2 p1 = u2f(acc[i][1]);
                const float2 p2 = u2f(acc[i][2]);
                const float2 p3 = u2f(acc[i][3]);
                float4 oA = {p0.x, p0.y, p1.x, p1.y};
                float4 oB = {p2.x, p2.y, p3.x, p3.y};
                *(float4*)(pout + (size_t)m * G4 + gidxA)        = oA;
                *(float4*)(pout + (size_t)m * G4 + gidxA + 2048) = oB;
            }
        }

        // ---------------- nb-group sync ----------------
        __threadfence();
        __syncthreads();
        if (tid == 0) {
            atomicAdd(&g_nbcnt[nb], 1u);
            while (atomicAdd(&g_nbcnt[nb], 0u) < 8u * (unsigned)(t + 1)) {
                __nanosleep(32);
            }
        }
        __syncthreads();

        // ---------------- Phase 2: combine (all blocks, 8 cols each) -------
        {
            float2 gate[4];
            #pragma unroll
            for (int g = 0; g < 4; g++) {
                const size_t off = (size_t)cb * G4 + (g << 10) + hcol;
                float2 s = *(const float2*)(g_xw + (size_t)t * BB * G4 + off);
                #pragma unroll
                for (int p = 0; p < NKB; p++) {
                    const float2 pv = __ldcg((const float2*)(g_part[p] + off));
                    s.x += pv.x; s.y += pv.y;
                }
                gate[g] = s;
            }

            const int idx = cb * HH + hcol;
            const float2 cp = *(const float2*)(g_c[par] + idx);
            float2 cn, hv;
            {
                const float iv = sigf(gate[0].x), fv = sigf(gate[1].x);
                const float gv = tanhfast(gate[2].x), ov = sigf(gate[3].x);
                cn.x = fv * cp.x + iv * gv;  hv.x = ov * tanhfast(cn.x);
            }
            {
                const float iv = sigf(gate[0].y), fv = sigf(gate[1].y);
                const float gv = tanhfast(gate[2].y), ov = sigf(gate[3].y);
                cn.y = fv * cp.y + iv * gv;  hv.y = ov * tanhfast(cn.y);
            }
            *(float2*)(g_c[par ^ 1] + idx) = cn;
            *(float2*)(out + (size_t)t * BHH + idx) = hv;
        }

        // ---------------- grid step barrier ----------------
        __threadfence();
        __syncthreads();
        if (tid == 0) {
            atomicAdd(&g_stepcnt, 1u);
            if (t + 1 < SS) {
                while (atomicAdd(&g_stepcnt, 0u) < 128u * (unsigned)(t + 1)) {
                    __nanosleep(32);
                }
            }
        }
        __syncthreads();
    }
}

// ---------------------------------------------------------------------------
// Helpers: seed c buffer + reset counters; emit h_t / c_t tails.
// ---------------------------------------------------------------------------
__global__ void copy_c0(const float* __restrict__ c0) {
    const int i = blockIdx.x * 256 + threadIdx.x;
    g_c[0][i] = c0[i];
    if (blockIdx.x == 0) {
        if (threadIdx.x < NNB) g_nbcnt[threadIdx.x] = 0u;
        if (threadIdx.x == NNB) g_stepcnt = 0u;
    }
}

__global__ void finalize(float* __restrict__ out) {
    const int i = blockIdx.x * 256 + threadIdx.x;
    const size_t base = (size_t)SS * BHH;
    out[base + i] = out[(size_t)(SS - 1) * BHH + i];   // h_t
    out[base + BHH + i] = g_c[0][i];                   // c_t (S even)
}

// ---------------------------------------------------------------------------
extern "C" void kernel_launch(void* const* d_in, const int* in_sizes, int n_in,
                              void* d_out, int out_size) {
    (void)in_sizes; (void)n_in; (void)out_size;
    const float* x  = (const float*)d_in[0];
    const float* h0 = (const float*)d_in[1];
    const float* c0 = (const float*)d_in[2];
    const float* Ww = (const float*)d_in[3];
    const float* Wb = (const float*)d_in[4];
    const float* Uw = (const float*)d_in[5];
    float* out = (float*)d_out;

    copy_c0<<<(BB * HH) / 256, 256>>>(c0);

    gemm_xw<<<dim3(G4 / 64, (SS * BB) / 64), 256>>>(x, Ww, Wb);

    lstm_persist<<<NNB * NKB, 256>>>(h0, Uw, out);

    finalize<<<(BB * HH) / 256, 256>>>(out);
}